// round 2
// baseline (speedup 1.0000x reference)
#include <cuda_runtime.h>
#include <math.h>

#define ROWS     512
#define NBASIS   256
#define RGRID    1024
#define QS       2048
#define NSLOTS   128
#define COLS_IN  512
#define SLOT_ELEMS (ROWS * RGRID)          // 524288
#define SLOT4      (SLOT_ELEMS / 4)        // 131072 = 2^17

// K = sqrt(0.5 * log2(e)) / H,  H = 0.1
#define KSCALE   8.49321999f
// 1 / (B * H * sqrt(2*pi))
#define INV_NORM 0.0155836865f
// window cut in K-scaled units: d^2 > 42 -> exp2(-42) ~ 2e-13 (natural exp < -29)
#define CUT      6.5f

// per-row partials: [row][part 0..3][ smin, smax, ymin, ymax ]
__device__ float g_part[ROWS * 4 * 4];

__device__ __forceinline__ float fwd_y(float s, int sl) {
    switch (sl) {
        case 0: return 2.0f * s;
        case 1: return s - 3.0f;
        case 2: { float ss = (fabsf(s) < 1e-6f) ? 1e-6f : s; return 1.0f / ss; }
        case 3: return 0.8f * s + 5.0f;
        case 4: {
            if (s >= 0.0f) { float e = expf(-s); return 1.0f / (1.0f + e); }
            else           { float e = expf(s);  return e / (1.0f + e); }
        }
        default: // softplus, stable
            return fmaxf(s, 0.0f) + log1pf(expf(-fabsf(s)));
    }
}

// 2048 blocks = 512 rows x 4 parts; each thread handles 2 q's.
// Only s-extremes per element (+ reciprocal extremes when sel==2);
// monotone transforms applied to the reduced extremes.
__global__ __launch_bounds__(256) void stats_kernel(
    const float* __restrict__ inputs,
    const float* __restrict__ noise,
    const int*   __restrict__ comp_idx,
    const int*   __restrict__ sel)
{
    int bid  = blockIdx.x;
    int r    = bid >> 2;
    int part = bid & 3;
    int t    = threadIdx.x;
    int sl   = __ldg(&sel[r]);

    const float* nzr = noise    + (size_t)r * QS + part * 512;
    const int*   cir = comp_idx + (size_t)r * QS + part * 512;

    float smn =  INFINITY, smx = -INFINITY;
    float rmn =  INFINITY, rmx = -INFINITY;   // reciprocal extremes (sel==2)

    #pragma unroll
    for (int i = 0; i < 2; i++) {
        int q = t + i * 256;
        int c = __ldg(&cir[q]);
        float sv = __ldg(&inputs[(size_t)c * COLS_IN + r]) + 0.1f * __ldg(&nzr[q]);
        smn = fminf(smn, sv);  smx = fmaxf(smx, sv);
        if (sl == 2) {
            float ss = (fabsf(sv) < 1e-6f) ? 1e-6f : sv;
            float y = 1.0f / ss;
            rmn = fminf(rmn, y);  rmx = fmaxf(rmx, y);
        }
    }

    __shared__ float red[4][8];
    #pragma unroll
    for (int o = 16; o > 0; o >>= 1) {
        smn = fminf(smn, __shfl_xor_sync(0xffffffffu, smn, o));
        smx = fmaxf(smx, __shfl_xor_sync(0xffffffffu, smx, o));
        rmn = fminf(rmn, __shfl_xor_sync(0xffffffffu, rmn, o));
        rmx = fmaxf(rmx, __shfl_xor_sync(0xffffffffu, rmx, o));
    }
    int w = t >> 5;
    if ((t & 31) == 0) { red[0][w] = smn; red[1][w] = smx; red[2][w] = rmn; red[3][w] = rmx; }
    __syncthreads();
    if (t == 0) {
        float a = red[0][0], b = red[1][0], c = red[2][0], d = red[3][0];
        #pragma unroll
        for (int i = 1; i < 8; i++) {
            a = fminf(a, red[0][i]); b = fmaxf(b, red[1][i]);
            c = fminf(c, red[2][i]); d = fmaxf(d, red[3][i]);
        }
        float ymn, ymx;
        if (sl == 2) { ymn = c; ymx = d; }
        else         { ymn = fwd_y(a, sl); ymx = fwd_y(b, sl); }
        float* dst = g_part + (r * 4 + part) * 4;
        dst[0] = a; dst[1] = b; dst[2] = ymn; dst[3] = ymx;
    }
}

__device__ __forceinline__ float ex2f_raw(float a) {
    float r;
    asm("ex2.approx.ftz.f32 %0, %1;" : "=f"(r) : "f"(a));
    return r;
}

// Even blocks: pdf compute for (row, type), window-pruned. Odd blocks: bank->out copy.
__global__ __launch_bounds__(256) void main_kernel(
    const float* __restrict__ inputs,
    const float* __restrict__ bank,
    const int*   __restrict__ sel,
    const int*   __restrict__ slot_p,
    float*       __restrict__ out)
{
    int slot_idx = slot_p ? __ldg(slot_p) : 37;
    int bid = blockIdx.x;
    int t   = threadIdx.x;

    if ((bid & 1) == 0) {
        // ---------- compute branch ----------
        int cid  = bid >> 1;        // 0..1023
        int row  = cid >> 1;        // 0..511
        int type = cid & 1;         // 0 = current, 1 = transformed

        __shared__ float xsK[NBASIS];
        xsK[t] = __ldg(&inputs[(size_t)t * COLS_IN + row]) * KSCALE;
        __syncthreads();

        // ---- bitonic sort xsK ascending (256 elems, 256 threads) ----
        #pragma unroll
        for (int k = 2; k <= NBASIS; k <<= 1) {
            for (int j = k >> 1; j > 0; j >>= 1) {
                int ixj = t ^ j;
                if (ixj > t) {
                    float a = xsK[t], b = xsK[ixj];
                    bool up = ((t & k) == 0);
                    if ((a > b) == up) { xsK[t] = b; xsK[ixj] = a; }
                }
                __syncthreads();
            }
        }

        // ---- row extremes from partials ----
        const float* p0 = g_part + row * 16;
        float mn, mx;
        {
            int off = type * 2;
            float a = p0[off], b = p0[off + 1];
            #pragma unroll
            for (int i = 1; i < 4; i++) {
                a = fminf(a, p0[i * 4 + off]);
                b = fmaxf(b, p0[i * 4 + off + 1]);
            }
            mn = a; mx = b;
        }
        float span = mx - mn;
        int sl = (type == 1) ? __ldg(&sel[row]) : -1;

        // ---- 4 consecutive grid points per thread ----
        float u[4], lf[4];
        float umn =  INFINITY, umx = -INFINITY;
        #pragma unroll
        for (int i = 0; i < 4; i++) {
            int j = 4 * t + i;
            float frac = (float)j / 1023.0f;
            float tg = mn + span * frac;
            if (tg == 0.0f) tg = 1e-7f;
            float xi, l;
            if (type == 0) { xi = tg; l = 1.0f; }
            else {
                switch (sl) {
                    case 0: xi = tg * 0.5f;          l = 0.5f;  break;
                    case 1: xi = tg + 3.0f;          l = 1.0f;  break;
                    case 2: xi = 1.0f / tg;          l = 1.0f / (tg * tg); break;
                    case 3: xi = (tg - 5.0f) / 0.8f; l = 1.25f; break;
                    case 4: {
                        float yc = fminf(fmaxf(tg, 1e-6f), 1.0f - 1e-6f);
                        xi = logf(yc) - log1pf(-yc);
                        l  = 1.0f / (yc * (1.0f - yc));
                        break;
                    }
                    default: {
                        float yp = fmaxf(tg, 1e-6f);
                        float em = expm1f(yp);
                        xi = logf(em);
                        l  = 1.0f / (-expm1f(-yp));
                        break;
                    }
                }
            }
            float uv = xi * KSCALE;
            u[i]  = uv;
            lf[i] = l;
            umn = fminf(umn, uv);
            umx = fmaxf(umx, uv);
        }

        // ---- warp-union window ----
        #pragma unroll
        for (int o = 16; o > 0; o >>= 1) {
            umn = fminf(umn, __shfl_xor_sync(0xffffffffu, umn, o));
            umx = fmaxf(umx, __shfl_xor_sync(0xffffffffu, umx, o));
        }
        float lowv  = umn - CUT;
        float highv = umx + CUT;

        int lo, hi;
        { int l = 0, r = NBASIS;
          while (l < r) { int m = (l + r) >> 1; if (xsK[m] < lowv)   l = m + 1; else r = m; }
          lo = l; }
        { int l = lo, r = NBASIS;
          while (l < r) { int m = (l + r) >> 1; if (xsK[m] <= highv) l = m + 1; else r = m; }
          hi = l; }

        float a0 = 0.f, a1 = 0.f, a2 = 0.f, a3 = 0.f;
        for (int b = lo; b < hi; b++) {
            float xv = xsK[b];                   // broadcast LDS
            float d0 = u[0] - xv;
            float d1 = u[1] - xv;
            float d2 = u[2] - xv;
            float d3 = u[3] - xv;
            a0 += ex2f_raw(-d0 * d0);
            a1 += ex2f_raw(-d1 * d1);
            a2 += ex2f_raw(-d2 * d2);
            a3 += ex2f_raw(-d3 * d3);
        }

        if (slot_idx != type) {
            float4 v;
            v.x = (a0 == 0.f) ? 0.f : a0 * INV_NORM * lf[0];
            v.y = (a1 == 0.f) ? 0.f : a1 * INV_NORM * lf[1];
            v.z = (a2 == 0.f) ? 0.f : a2 * INV_NORM * lf[2];
            v.w = (a3 == 0.f) ? 0.f : a3 * INV_NORM * lf[3];
            float4* dst = (float4*)(out + (size_t)type * SLOT_ELEMS + (size_t)row * RGRID);
            dst[t] = v;
        }
    } else {
        // ---------- copy branch ----------
        int cb = bid >> 1;          // 0..1023
        const float4* src4 = (const float4*)bank;
        float4*       dst4 = (float4*)out;
        const long total4 = (long)NSLOTS * SLOT4;   // 16,777,216
        const long stride = 1024L * 256L;
        for (long idx = (long)cb * 256 + t; idx < total4; idx += stride) {
            int  s   = (int)(idx >> 17);        // slot (SLOT4 = 2^17)
            long off = idx & (long)(SLOT4 - 1);
            int  srcs;
            if (s == slot_idx)      srcs = 0;   // out[slot_idx] = prev = bank[0]
            else if (s < 2)         continue;   // slots 0/1 written by compute blocks
            else                    srcs = s;
            float4 v = __ldcs(&src4[(long)srcs * SLOT4 + off]);
            __stcs(&dst4[idx], v);
        }
    }
}

extern "C" void kernel_launch(void* const* d_in, const int* in_sizes, int n_in,
                              void* d_out, int out_size)
{
    const float* inputs   = (const float*)d_in[0];
    const float* bank     = (const float*)d_in[1];
    const float* noise    = (const float*)d_in[2];
    const int*   comp_idx = (const int*)  d_in[3];
    const int*   sel      = (const int*)  d_in[4];
    const int*   slot_p   = (n_in >= 6) ? (const int*)d_in[5] : nullptr;
    float* out = (float*)d_out;

    stats_kernel<<<ROWS * 4, 256>>>(inputs, noise, comp_idx, sel);
    main_kernel<<<2048, 256>>>(inputs, bank, sel, slot_p, out);
}

// round 5
// speedup vs baseline: 1.0789x; 1.0789x over previous
#include <cuda_runtime.h>
#include <math.h>

#define ROWS     512
#define NBASIS   256
#define RGRID    1024
#define QS       2048
#define NSLOTS   128
#define COLS_IN  512
#define SLOT_ELEMS (ROWS * RGRID)          // 524288
#define SLOT4      (SLOT_ELEMS / 4)        // 131072 = 2^17
#define CHUNK4   16384                     // float4 per copy block (8 blocks/slot)

// K = sqrt(0.5 * log2(e)) / H,  H = 0.1
#define KSCALE   8.49321999f
// 1 / (B * H * sqrt(2*pi))
#define INV_NORM 0.0155836865f
// window cut in K-scaled units: exp2(-CUT^2) ~ 2e-13
#define CUT      6.5f

// per-row partials: [row][part 0..3][ smin, smax, ymin, ymax ]
__device__ float g_part[ROWS * 4 * 4];

__device__ __forceinline__ float fwd_y(float s, int sl) {
    switch (sl) {
        case 0: return 2.0f * s;
        case 1: return s - 3.0f;
        case 2: { float ss = (fabsf(s) < 1e-6f) ? 1e-6f : s; return 1.0f / ss; }
        case 3: return 0.8f * s + 5.0f;
        case 4: {
            if (s >= 0.0f) { float e = expf(-s); return 1.0f / (1.0f + e); }
            else           { float e = expf(s);  return e / (1.0f + e); }
        }
        default: // softplus, stable
            return fmaxf(s, 0.0f) + log1pf(expf(-fabsf(s)));
    }
}

__global__ __launch_bounds__(256) void stats_kernel(
    const float* __restrict__ inputs,
    const float* __restrict__ noise,
    const int*   __restrict__ comp_idx,
    const int*   __restrict__ sel)
{
    int bid  = blockIdx.x;
    int r    = bid >> 2;
    int part = bid & 3;
    int t    = threadIdx.x;
    int sl   = __ldg(&sel[r]);

    const float* nzr = noise    + (size_t)r * QS + part * 512;
    const int*   cir = comp_idx + (size_t)r * QS + part * 512;

    float smn =  INFINITY, smx = -INFINITY;
    float rmn =  INFINITY, rmx = -INFINITY;   // reciprocal extremes (sel==2)

    #pragma unroll
    for (int i = 0; i < 2; i++) {
        int q = t + i * 256;
        int c = __ldg(&cir[q]);
        float sv = __ldg(&inputs[(size_t)c * COLS_IN + r]) + 0.1f * __ldg(&nzr[q]);
        smn = fminf(smn, sv);  smx = fmaxf(smx, sv);
        if (sl == 2) {
            float ss = (fabsf(sv) < 1e-6f) ? 1e-6f : sv;
            float y = 1.0f / ss;
            rmn = fminf(rmn, y);  rmx = fmaxf(rmx, y);
        }
    }

    __shared__ float red[4][8];
    #pragma unroll
    for (int o = 16; o > 0; o >>= 1) {
        smn = fminf(smn, __shfl_xor_sync(0xffffffffu, smn, o));
        smx = fmaxf(smx, __shfl_xor_sync(0xffffffffu, smx, o));
        rmn = fminf(rmn, __shfl_xor_sync(0xffffffffu, rmn, o));
        rmx = fmaxf(rmx, __shfl_xor_sync(0xffffffffu, rmx, o));
    }
    int w = t >> 5;
    if ((t & 31) == 0) { red[0][w] = smn; red[1][w] = smx; red[2][w] = rmn; red[3][w] = rmx; }
    __syncthreads();
    if (t == 0) {
        float a = red[0][0], b = red[1][0], c = red[2][0], d = red[3][0];
        #pragma unroll
        for (int i = 1; i < 8; i++) {
            a = fminf(a, red[0][i]); b = fmaxf(b, red[1][i]);
            c = fminf(c, red[2][i]); d = fmaxf(d, red[3][i]);
        }
        float ymn, ymx;
        if (sl == 2) { ymn = c; ymx = d; }
        else         { ymn = fwd_y(a, sl); ymx = fwd_y(b, sl); }
        float* dst = g_part + (r * 4 + part) * 4;
        dst[0] = a; dst[1] = b; dst[2] = ymn; dst[3] = ymx;
    }
}

__device__ __forceinline__ float ex2f_raw(float a) {
    float r;
    asm("ex2.approx.ftz.f32 %0, %1;" : "=f"(r) : "f"(a));
    return r;
}

// Even blocks: pdf compute for (row, type), window-pruned.
// Odd blocks: contiguous-chunk bank->out copy (plain LDG/STG.128).
__global__ __launch_bounds__(256) void main_kernel(
    const float* __restrict__ inputs,
    const float* __restrict__ bank,
    const int*   __restrict__ sel,
    const int*   __restrict__ slot_p,
    float*       __restrict__ out)
{
    int slot_idx = slot_p ? __ldg(slot_p) : 37;
    int bid = blockIdx.x;
    int t   = threadIdx.x;

    if ((bid & 1) == 0) {
        // ---------- compute branch ----------
        int cid  = bid >> 1;        // 0..1023
        int row  = cid >> 1;        // 0..511
        int type = cid & 1;         // 0 = current, 1 = transformed

        __shared__ float xsK[NBASIS];
        xsK[t] = __ldg(&inputs[(size_t)t * COLS_IN + row]) * KSCALE;
        __syncthreads();

        // ---- bitonic sort xsK ascending ----
        #pragma unroll
        for (int k = 2; k <= NBASIS; k <<= 1) {
            for (int j = k >> 1; j > 0; j >>= 1) {
                int ixj = t ^ j;
                if (ixj > t) {
                    float a = xsK[t], b = xsK[ixj];
                    bool up = ((t & k) == 0);
                    if ((a > b) == up) { xsK[t] = b; xsK[ixj] = a; }
                }
                __syncthreads();
            }
        }

        // ---- row extremes from partials ----
        const float* p0 = g_part + row * 16;
        float mn, mx;
        {
            int off = type * 2;
            float a = p0[off], b = p0[off + 1];
            #pragma unroll
            for (int i = 1; i < 4; i++) {
                a = fminf(a, p0[i * 4 + off]);
                b = fmaxf(b, p0[i * 4 + off + 1]);
            }
            mn = a; mx = b;
        }
        float span = mx - mn;
        int sl = (type == 1) ? __ldg(&sel[row]) : -1;

        // ---- 4 consecutive grid points per thread ----
        float u[4], lf[4];
        float umn =  INFINITY, umx = -INFINITY;
        #pragma unroll
        for (int i = 0; i < 4; i++) {
            int j = 4 * t + i;
            float frac = (float)j / 1023.0f;
            float tg = mn + span * frac;
            if (tg == 0.0f) tg = 1e-7f;
            float xi, l;
            if (type == 0) { xi = tg; l = 1.0f; }
            else {
                switch (sl) {
                    case 0: xi = tg * 0.5f;          l = 0.5f;  break;
                    case 1: xi = tg + 3.0f;          l = 1.0f;  break;
                    case 2: xi = 1.0f / tg;          l = 1.0f / (tg * tg); break;
                    case 3: xi = (tg - 5.0f) / 0.8f; l = 1.25f; break;
                    case 4: {
                        float yc = fminf(fmaxf(tg, 1e-6f), 1.0f - 1e-6f);
                        xi = logf(yc) - log1pf(-yc);
                        l  = 1.0f / (yc * (1.0f - yc));
                        break;
                    }
                    default: {
                        float yp = fmaxf(tg, 1e-6f);
                        float em = expm1f(yp);
                        xi = logf(em);
                        l  = 1.0f / (-expm1f(-yp));
                        break;
                    }
                }
            }
            float uv = xi * KSCALE;
            u[i]  = uv;
            lf[i] = l;
            umn = fminf(umn, uv);
            umx = fmaxf(umx, uv);
        }

        // ---- warp-union window ----
        #pragma unroll
        for (int o = 16; o > 0; o >>= 1) {
            umn = fminf(umn, __shfl_xor_sync(0xffffffffu, umn, o));
            umx = fmaxf(umx, __shfl_xor_sync(0xffffffffu, umx, o));
        }
        float lowv  = umn - CUT;
        float highv = umx + CUT;

        int lo, hi;
        { int l = 0, r = NBASIS;
          while (l < r) { int m = (l + r) >> 1; if (xsK[m] < lowv)   l = m + 1; else r = m; }
          lo = l; }
        { int l = lo, r = NBASIS;
          while (l < r) { int m = (l + r) >> 1; if (xsK[m] <= highv) l = m + 1; else r = m; }
          hi = l; }

        float a0 = 0.f, a1 = 0.f, a2 = 0.f, a3 = 0.f;
        for (int b = lo; b < hi; b++) {
            float xv = xsK[b];                   // broadcast LDS
            float d0 = u[0] - xv;
            float d1 = u[1] - xv;
            float d2 = u[2] - xv;
            float d3 = u[3] - xv;
            a0 += ex2f_raw(-d0 * d0);
            a1 += ex2f_raw(-d1 * d1);
            a2 += ex2f_raw(-d2 * d2);
            a3 += ex2f_raw(-d3 * d3);
        }

        if (slot_idx != type) {
            float4 v;
            v.x = (a0 == 0.f) ? 0.f : a0 * INV_NORM * lf[0];
            v.y = (a1 == 0.f) ? 0.f : a1 * INV_NORM * lf[1];
            v.z = (a2 == 0.f) ? 0.f : a2 * INV_NORM * lf[2];
            v.w = (a3 == 0.f) ? 0.f : a3 * INV_NORM * lf[3];
            float4* dst = (float4*)(out + (size_t)type * SLOT_ELEMS + (size_t)row * RGRID);
            dst[t] = v;
        }
    } else {
        // ---------- copy branch: one contiguous chunk per block ----------
        int cb = bid >> 1;          // 0..1023
        int s  = cb >> 3;           // slot 0..127 (8 blocks per slot)
        int srcs;
        if (s == slot_idx)      srcs = 0;      // out[slot_idx] = prev = bank[0]
        else if (s < 2)         return;        // slots 0/1 written by compute blocks
        else                    srcs = s;

        long coff = (long)(cb & 7) * CHUNK4;
        const float4* __restrict__ src = (const float4*)bank + (long)srcs * SLOT4 + coff;
        float4*       __restrict__ dst = (float4*)out        + (long)s    * SLOT4 + coff;

        #pragma unroll 4
        for (int i = t; i < CHUNK4; i += 256) {
            dst[i] = src[i];
        }
    }
}

extern "C" void kernel_launch(void* const* d_in, const int* in_sizes, int n_in,
                              void* d_out, int out_size)
{
    const float* inputs   = (const float*)d_in[0];
    const float* bank     = (const float*)d_in[1];
    const float* noise    = (const float*)d_in[2];
    const int*   comp_idx = (const int*)  d_in[3];
    const int*   sel      = (const int*)  d_in[4];
    const int*   slot_p   = (n_in >= 6) ? (const int*)d_in[5] : nullptr;
    float* out = (float*)d_out;

    stats_kernel<<<ROWS * 4, 256>>>(inputs, noise, comp_idx, sel);
    main_kernel<<<2048, 256>>>(inputs, bank, sel, slot_p, out);
}

// round 6
// speedup vs baseline: 1.1870x; 1.1002x over previous
#include <cuda_runtime.h>
#include <math.h>

#define ROWS     512
#define NBASIS   256
#define RGRID    1024
#define QS       2048
#define NSLOTS   128
#define COLS_IN  512
#define SLOT_ELEMS (ROWS * RGRID)          // 524288
#define SLOT4      (SLOT_ELEMS / 4)        // 131072 = 2^17
#define CHUNK4   16384                     // float4 per copy block (8 blocks/slot)

// K = sqrt(0.5 * log2(e)) / H,  H = 0.1
#define KSCALE   8.49321999f
// 1 / (B * H * sqrt(2*pi))
#define INV_NORM 0.0155836865f
// window cut in K-scaled units: exp2(-CUT^2) ~ 2e-13
#define CUT      6.5f

__device__ __forceinline__ float fwd_y(float s, int sl) {
    switch (sl) {
        case 0: return 2.0f * s;
        case 1: return s - 3.0f;
        case 2: { float ss = (fabsf(s) < 1e-6f) ? 1e-6f : s; return 1.0f / ss; }
        case 3: return 0.8f * s + 5.0f;
        case 4: {
            if (s >= 0.0f) { float e = expf(-s); return 1.0f / (1.0f + e); }
            else           { float e = expf(s);  return e / (1.0f + e); }
        }
        default: // softplus, stable
            return fmaxf(s, 0.0f) + log1pf(expf(-fabsf(s)));
    }
}

__device__ __forceinline__ float ex2f_raw(float a) {
    float r;
    asm("ex2.approx.ftz.f32 %0, %1;" : "=f"(r) : "f"(a));
    return r;
}

// Even blocks: fused stats + pdf compute for (row, type), window-pruned.
// Odd blocks: contiguous-chunk bank->out copy (plain LDG/STG.128).
__global__ __launch_bounds__(256) void main_kernel(
    const float* __restrict__ inputs,
    const float* __restrict__ bank,
    const float* __restrict__ noise,
    const int*   __restrict__ comp_idx,
    const int*   __restrict__ sel,
    const int*   __restrict__ slot_p,
    float*       __restrict__ out)
{
    int slot_idx = slot_p ? __ldg(slot_p) : 37;
    int bid = blockIdx.x;
    int t   = threadIdx.x;

    if ((bid & 1) == 0) {
        // ---------- compute branch ----------
        int cid  = bid >> 1;        // 0..1023
        int row  = cid >> 1;        // 0..511
        int type = cid & 1;         // 0 = current, 1 = transformed

        __shared__ float xsK[NBASIS];
        __shared__ float red[2][8];
        __shared__ float mnmx[2];

        // raw basis values (needed for the sample gather)
        xsK[t] = __ldg(&inputs[(size_t)t * COLS_IN + row]);
        __syncthreads();

        int sl = (type == 1) ? __ldg(&sel[row]) : -1;

        // ---- fused stats: this block's own extreme (s for type0 / y for type1) ----
        {
            const float* nzr = noise    + (size_t)row * QS;
            const int*   cir = comp_idx + (size_t)row * QS;

            float emn =  INFINITY, emx = -INFINITY;
            bool  recip = (type == 1 && sl == 2);

            #pragma unroll
            for (int i = 0; i < 8; i++) {
                int q = t + i * 256;
                int c = __ldg(&cir[q]);
                float sv = xsK[c] + 0.1f * __ldg(&nzr[q]);
                if (recip) {
                    float ss = (fabsf(sv) < 1e-6f) ? 1e-6f : sv;
                    float y = 1.0f / ss;
                    emn = fminf(emn, y);  emx = fmaxf(emx, y);
                } else {
                    emn = fminf(emn, sv); emx = fmaxf(emx, sv);
                }
            }
            #pragma unroll
            for (int o = 16; o > 0; o >>= 1) {
                emn = fminf(emn, __shfl_xor_sync(0xffffffffu, emn, o));
                emx = fmaxf(emx, __shfl_xor_sync(0xffffffffu, emx, o));
            }
            int w = t >> 5;
            if ((t & 31) == 0) { red[0][w] = emn; red[1][w] = emx; }
            __syncthreads();
            if (t == 0) {
                float a = red[0][0], b = red[1][0];
                #pragma unroll
                for (int i = 1; i < 8; i++) {
                    a = fminf(a, red[0][i]); b = fmaxf(b, red[1][i]);
                }
                if (type == 1 && sl != 2) { a = fwd_y(a, sl); b = fwd_y(b, sl); }
                mnmx[0] = a; mnmx[1] = b;
            }
        }

        // scale basis in place, then sort
        __syncthreads();
        float scaled = xsK[t] * KSCALE;
        __syncthreads();
        xsK[t] = scaled;
        __syncthreads();

        // ---- bitonic sort xsK ascending ----
        #pragma unroll
        for (int k = 2; k <= NBASIS; k <<= 1) {
            for (int j = k >> 1; j > 0; j >>= 1) {
                int ixj = t ^ j;
                if (ixj > t) {
                    float a = xsK[t], b = xsK[ixj];
                    bool up = ((t & k) == 0);
                    if ((a > b) == up) { xsK[t] = b; xsK[ixj] = a; }
                }
                __syncthreads();
            }
        }

        float mn = mnmx[0], mx = mnmx[1];
        float span = mx - mn;

        // ---- 4 consecutive grid points per thread ----
        float u[4], lf[4];
        float umn =  INFINITY, umx = -INFINITY;
        #pragma unroll
        for (int i = 0; i < 4; i++) {
            int j = 4 * t + i;
            float frac = (float)j / 1023.0f;
            float tg = mn + span * frac;
            if (tg == 0.0f) tg = 1e-7f;
            float xi, l;
            if (type == 0) { xi = tg; l = 1.0f; }
            else {
                switch (sl) {
                    case 0: xi = tg * 0.5f;          l = 0.5f;  break;
                    case 1: xi = tg + 3.0f;          l = 1.0f;  break;
                    case 2: xi = 1.0f / tg;          l = 1.0f / (tg * tg); break;
                    case 3: xi = (tg - 5.0f) / 0.8f; l = 1.25f; break;
                    case 4: {
                        float yc = fminf(fmaxf(tg, 1e-6f), 1.0f - 1e-6f);
                        xi = logf(yc) - log1pf(-yc);
                        l  = 1.0f / (yc * (1.0f - yc));
                        break;
                    }
                    default: {
                        float yp = fmaxf(tg, 1e-6f);
                        float em = expm1f(yp);
                        xi = logf(em);
                        l  = 1.0f / (-expm1f(-yp));
                        break;
                    }
                }
            }
            float uv = xi * KSCALE;
            u[i]  = uv;
            lf[i] = l;
            umn = fminf(umn, uv);
            umx = fmaxf(umx, uv);
        }

        // ---- warp-union window ----
        #pragma unroll
        for (int o = 16; o > 0; o >>= 1) {
            umn = fminf(umn, __shfl_xor_sync(0xffffffffu, umn, o));
            umx = fmaxf(umx, __shfl_xor_sync(0xffffffffu, umx, o));
        }
        float lowv  = umn - CUT;
        float highv = umx + CUT;

        int lo, hi;
        { int l = 0, r = NBASIS;
          while (l < r) { int m = (l + r) >> 1; if (xsK[m] < lowv)   l = m + 1; else r = m; }
          lo = l; }
        { int l = lo, r = NBASIS;
          while (l < r) { int m = (l + r) >> 1; if (xsK[m] <= highv) l = m + 1; else r = m; }
          hi = l; }

        float a0 = 0.f, a1 = 0.f, a2 = 0.f, a3 = 0.f;
        for (int b = lo; b < hi; b++) {
            float xv = xsK[b];                   // broadcast LDS
            float d0 = u[0] - xv;
            float d1 = u[1] - xv;
            float d2 = u[2] - xv;
            float d3 = u[3] - xv;
            a0 += ex2f_raw(-d0 * d0);
            a1 += ex2f_raw(-d1 * d1);
            a2 += ex2f_raw(-d2 * d2);
            a3 += ex2f_raw(-d3 * d3);
        }

        if (slot_idx != type) {
            float4 v;
            v.x = (a0 == 0.f) ? 0.f : a0 * INV_NORM * lf[0];
            v.y = (a1 == 0.f) ? 0.f : a1 * INV_NORM * lf[1];
            v.z = (a2 == 0.f) ? 0.f : a2 * INV_NORM * lf[2];
            v.w = (a3 == 0.f) ? 0.f : a3 * INV_NORM * lf[3];
            float4* dst = (float4*)(out + (size_t)type * SLOT_ELEMS + (size_t)row * RGRID);
            dst[t] = v;
        }
    } else {
        // ---------- copy branch: one contiguous chunk per block ----------
        int cb = bid >> 1;          // 0..1023
        int s  = cb >> 3;           // slot 0..127 (8 blocks per slot)
        int srcs;
        if (s == slot_idx)      srcs = 0;      // out[slot_idx] = prev = bank[0]
        else if (s < 2)         return;        // slots 0/1 written by compute blocks
        else                    srcs = s;

        long coff = (long)(cb & 7) * CHUNK4;
        const float4* __restrict__ src = (const float4*)bank + (long)srcs * SLOT4 + coff;
        float4*       __restrict__ dst = (float4*)out        + (long)s    * SLOT4 + coff;

        #pragma unroll 8
        for (int i = t; i < CHUNK4; i += 256) {
            dst[i] = src[i];
        }
    }
}

extern "C" void kernel_launch(void* const* d_in, const int* in_sizes, int n_in,
                              void* d_out, int out_size)
{
    const float* inputs   = (const float*)d_in[0];
    const float* bank     = (const float*)d_in[1];
    const float* noise    = (const float*)d_in[2];
    const int*   comp_idx = (const int*)  d_in[3];
    const int*   sel      = (const int*)  d_in[4];
    const int*   slot_p   = (n_in >= 6) ? (const int*)d_in[5] : nullptr;
    float* out = (float*)d_out;

    main_kernel<<<2048, 256>>>(inputs, bank, noise, comp_idx, sel, slot_p, out);
}